// round 7
// baseline (speedup 1.0000x reference)
#include <cuda_runtime.h>
#include <cuda_bf16.h>
#include <cstdint>
#include <math.h>

// ---------------- problem constants ----------------
#define S_    3
#define B_    1024
#define D_    64
#define H_    128
#define O_    128
#define T_    64
#define NROW  3072                    // S_*B_
#define NELEM (NROW * D_)             // 196608
#define RTOL_ 1e-4f
#define ATOL_ 1e-5f
#define MAX_INNER 12

// ---------------- kernel config ----------------
#define NCTA 128
#define TPB  256                      // 8 warps, 2 per SMSP
#define RPC  24                       // rows per CTA
#define PPC  12                       // row-pairs per CTA
#define NGRP 4                        // warp pairs per CTA
#define PPG  3                        // row-pairs per group

typedef unsigned long long u64;

// ---------------- packed f32x2 helpers ----------------
__device__ __forceinline__ u64 ffma2(u64 a, u64 b, u64 c) {
    u64 d; asm("fma.rn.f32x2 %0, %1, %2, %3;" : "=l"(d) : "l"(a), "l"(b), "l"(c)); return d;
}
__device__ __forceinline__ u64 dup2(float v) {
    u64 r; asm("mov.b64 %0, {%1, %1};" : "=l"(r) : "f"(v)); return r;
}
__device__ __forceinline__ u64 pack2(float a, float b) {
    u64 r; asm("mov.b64 %0, {%1, %2};" : "=l"(r) : "f"(a), "f"(b)); return r;
}
__device__ __forceinline__ float2 u2f2(u64 v) {
    float2 f; asm("mov.b64 {%0, %1}, %2;" : "=f"(f.x), "=f"(f.y) : "l"(v)); return f;
}
__device__ __forceinline__ void bar_pair(int g) {
    asm volatile("bar.sync %0, %1;" :: "r"(g + 1), "r"(64) : "memory");
}

// ---------------- shared memory layout (all pair-packed u64 state) ----------------
struct __align__(16) Smem {
    float W1[D_][H_];        // 32 KB   (d-major)
    float W2[H_][D_];        // 32 KB   (j-major)
    float b1[H_];
    float b2[D_];
    u64 Yp [PPC][D_];        // 6 KB  {row 2p, row 2p+1}
    u64 Y5p[PPC][D_];        // 6 KB
    u64 Ytp[PPC][D_];        // 6 KB
    u64 Hp [PPC][H_];        // 12 KB
    u64 Kp [7][PPC][D_];     // 42 KB
    float red[TPB];          // 1 KB
    float s_ratio;
};
#define SMEM_BYTES ((int)sizeof(Smem))

// ---------------- device globals (scratch; no allocations allowed) ----------------
__device__ unsigned g_bar = 0;                         // monotone barrier counter
__device__ float    g_part[2][NCTA];                   // per-CTA partial err sums
__device__ float    g_sol[(size_t)NROW * T_ * D_];     // fallback sol_z scratch

// ---------------- grid-wide barrier (all NCTA CTAs co-resident) ----------------
__device__ __forceinline__ void grid_barrier(int tid) {
    __syncthreads();
    if (tid == 0) {
        __threadfence();
        unsigned arrival = atomicAdd(&g_bar, 1u);
        unsigned target = arrival - (arrival % NCTA) + NCTA;
        while ((int)(*(volatile unsigned*)&g_bar - target) < 0) {
            __nanosleep(64);
        }
        __threadfence();
    }
    __syncthreads();
}

// ---------------- f(Yin) -> Kout : pair-packed, col-split across warp pair ----------
// group g owns pairs 3g..3g+2 (rows 6g..6g+5); warp half h:
//   stage A: cols 64h+2l, 64h+2l+1 of H     stage B: col 32h+l of D
__device__ __forceinline__ void feval(Smem* s, int g, int h, int l,
                                      const u64 (*Yin)[D_], u64 (*Kout)[D_]) {
    bar_pair(g);                               // Yin fully written by pair
    const int p0 = PPG * g;
    const int cA = 64 * h + 2 * l;
    const int cB = 32 * h + l;

    // ---- stage A: Hp = tanh(Yin @ W1 + b1) ----
    u64 a0[PPG], a1[PPG];
    {
        u64 i0 = dup2(s->b1[cA]), i1 = dup2(s->b1[cA + 1]);
        #pragma unroll
        for (int pp = 0; pp < PPG; pp++) { a0[pp] = i0; a1[pp] = i1; }
    }
    #pragma unroll 8
    for (int d0 = 0; d0 < D_; d0 += 2) {
        float2 wa = *(const float2*)&s->W1[d0][cA];       // LDS.64 conflict-free
        float2 wb = *(const float2*)&s->W1[d0 + 1][cA];
        u64 wa0 = dup2(wa.x), wa1 = dup2(wa.y);
        u64 wb0 = dup2(wb.x), wb1 = dup2(wb.y);
        #pragma unroll
        for (int pp = 0; pp < PPG; pp++) {
            ulonglong2 yq = *(const ulonglong2*)&Yin[p0 + pp][d0];   // bc LDS.128
            a0[pp] = ffma2(yq.x, wa0, a0[pp]);
            a1[pp] = ffma2(yq.x, wa1, a1[pp]);
            a0[pp] = ffma2(yq.y, wb0, a0[pp]);
            a1[pp] = ffma2(yq.y, wb1, a1[pp]);
        }
    }
    #pragma unroll
    for (int pp = 0; pp < PPG; pp++) {
        float2 v0 = u2f2(a0[pp]), v1 = u2f2(a1[pp]);
        ulonglong2 hq;
        hq.x = pack2(tanhf(v0.x), tanhf(v0.y));
        hq.y = pack2(tanhf(v1.x), tanhf(v1.y));
        *(ulonglong2*)&s->Hp[p0 + pp][cA] = hq;           // STS.128 conflict-free
    }
    bar_pair(g);                               // Hp fully written by pair

    // ---- stage B: Kout = Hp @ W2 + b2 ----
    u64 acc[PPG];
    {
        u64 ib = dup2(s->b2[cB]);
        #pragma unroll
        for (int pp = 0; pp < PPG; pp++) acc[pp] = ib;
    }
    #pragma unroll 8
    for (int j0 = 0; j0 < H_; j0 += 2) {
        u64 wd0 = dup2(s->W2[j0][cB]);                    // LDS.32 conflict-free
        u64 wd1 = dup2(s->W2[j0 + 1][cB]);
        #pragma unroll
        for (int pp = 0; pp < PPG; pp++) {
            ulonglong2 hq = *(const ulonglong2*)&s->Hp[p0 + pp][j0]; // bc LDS.128
            acc[pp] = ffma2(hq.x, wd0, acc[pp]);
            acc[pp] = ffma2(hq.y, wd1, acc[pp]);
        }
    }
    #pragma unroll
    for (int pp = 0; pp < PPG; pp++)
        Kout[p0 + pp][cB] = acc[pp];                      // same-thread consumers
}

// ---- Out[p][cB] = Y + dt * sum(cf[kk]*K[kk]) ; thread-local ownership ----
template <int NK>
__device__ __forceinline__ void build_pair(Smem* s, int p0, int cB, u64 dtd,
                                           const float* cf, u64 (*Out)[D_]) {
    #pragma unroll
    for (int pp = 0; pp < PPG; pp++) {
        const int p = p0 + pp;
        u64 acc = 0ULL;
        #pragma unroll
        for (int kk = 0; kk < NK; kk++)
            acc = ffma2(dup2(cf[kk]), s->Kp[kk][p][cB], acc);
        Out[p][cB] = ffma2(dtd, acc, s->Yp[p][cB]);
    }
}

// ---------------- persistent ODE solver kernel ----------------
__global__ void __launch_bounds__(TPB, 1)
ode_kernel(const float* __restrict__ first_point,
           const float* __restrict__ times,
           const float* __restrict__ gW1, const float* __restrict__ gb1,
           const float* __restrict__ gW2, const float* __restrict__ gb2,
           float* __restrict__ sol) {
    extern __shared__ char smem_raw[];
    Smem* s = (Smem*)smem_raw;

    const int tid = threadIdx.x;
    const int w = tid >> 5;
    const int l = tid & 31;
    const int g = w >> 1;
    const int h = w & 1;
    const int row0 = blockIdx.x * RPC;
    const int p0 = PPG * g;
    const int cB = 32 * h + l;

    // load weights + initial state (pair-packed)
    for (int i = tid; i < D_ * H_; i += TPB) ((float*)s->W1)[i] = gW1[i];
    for (int i = tid; i < H_ * D_; i += TPB) ((float*)s->W2)[i] = gW2[i];
    for (int i = tid; i < H_; i += TPB) s->b1[i] = gb1[i];
    for (int i = tid; i < D_; i += TPB) s->b2[i] = gb2[i];
    for (int i = tid; i < RPC * D_; i += TPB) {
        int row = i / D_, d = i % D_;
        float v = first_point[(size_t)(row0 + row) * D_ + d];
        ((float*)&s->Yp[row >> 1][d])[row & 1] = v;
    }
    __syncthreads();

    // sol at t index 0 (coalesced 128B rows)
    #pragma unroll
    for (int pp = 0; pp < PPG; pp++) {
        float2 f = u2f2(s->Yp[p0 + pp][cB]);
        const size_t rg = (size_t)(row0 + 2 * (p0 + pp));
        sol[(rg * T_ + 0) * D_ + cB]       = f.x;
        sol[((rg + 1) * T_ + 0) * D_ + cB] = f.y;
    }

    // dopri5 coefficients
    const float C2[1] = {0.2f};
    const float C3[2] = {3.f / 40.f, 9.f / 40.f};
    const float C4[3] = {44.f / 45.f, -56.f / 15.f, 32.f / 9.f};
    const float C5[4] = {19372.f / 6561.f, -25360.f / 2187.f, 64448.f / 6561.f, -212.f / 729.f};
    const float C6[5] = {9017.f / 3168.f, -355.f / 33.f, 46732.f / 5247.f, 49.f / 176.f,
                         -5103.f / 18656.f};
    const float CB[6] = {35.f / 384.f, 0.f, 500.f / 1113.f, 125.f / 192.f,
                         -2187.f / 6784.f, 11.f / 84.f};

    float t  = times[0];
    float dt = times[1] - times[0];
    int sc = 0;

    for (int ti = 0; ti < T_ - 1; ti++) {
        const float t_target = times[ti + 1];

        for (int iter = 0; iter < MAX_INNER; iter++) {
            const float remaining = t_target - t;
            if (remaining <= 0.0f) break;              // remaining iters are exact no-ops
            const float dt_try = fminf(dt, remaining);
            const u64 dtd = dup2(dt_try);

            // 7 stages
            feval(s, g, h, l, s->Yp, s->Kp[0]);
            build_pair<1>(s, p0, cB, dtd, C2, s->Ytp); feval(s, g, h, l, s->Ytp, s->Kp[1]);
            build_pair<2>(s, p0, cB, dtd, C3, s->Ytp); feval(s, g, h, l, s->Ytp, s->Kp[2]);
            build_pair<3>(s, p0, cB, dtd, C4, s->Ytp); feval(s, g, h, l, s->Ytp, s->Kp[3]);
            build_pair<4>(s, p0, cB, dtd, C5, s->Ytp); feval(s, g, h, l, s->Ytp, s->Kp[4]);
            build_pair<5>(s, p0, cB, dtd, C6, s->Ytp); feval(s, g, h, l, s->Ytp, s->Kp[5]);
            build_pair<6>(s, p0, cB, dtd, CB, s->Y5p); feval(s, g, h, l, s->Y5p, s->Kp[6]);

            // local error accumulation (thread-local elements: 3 pairs x 1 col)
            const u64 E1d = dup2(71.f / 57600.f);
            const u64 E3d = dup2(-71.f / 16695.f);
            const u64 E4d = dup2(71.f / 1920.f);
            const u64 E5d = dup2(-17253.f / 339200.f);
            const u64 E6d = dup2(22.f / 525.f);
            const u64 E7d = dup2(-1.f / 40.f);
            float local = 0.f;
            #pragma unroll
            for (int pp = 0; pp < PPG; pp++) {
                const int p = p0 + pp;
                u64 e = ffma2(E1d, s->Kp[0][p][cB], 0ULL);
                e = ffma2(E3d, s->Kp[2][p][cB], e);
                e = ffma2(E4d, s->Kp[3][p][cB], e);
                e = ffma2(E5d, s->Kp[4][p][cB], e);
                e = ffma2(E6d, s->Kp[5][p][cB], e);
                e = ffma2(E7d, s->Kp[6][p][cB], e);
                e = ffma2(dtd, e, 0ULL);
                float2 ef = u2f2(e);
                float2 yf = u2f2(s->Yp[p][cB]);
                float2 y5f = u2f2(s->Y5p[p][cB]);
                {
                    float scale = ATOL_ + RTOL_ * fmaxf(fabsf(yf.x), fabsf(y5f.x));
                    float q = ef.x / scale;
                    local = fmaf(q, q, local);
                }
                {
                    float scale = ATOL_ + RTOL_ * fmaxf(fabsf(yf.y), fabsf(y5f.y));
                    float q = ef.y / scale;
                    local = fmaf(q, q, local);
                }
            }

            // deterministic CTA tree reduction
            s->red[tid] = local;
            __syncthreads();
            #pragma unroll
            for (int off = TPB / 2; off > 0; off >>= 1) {
                if (tid < off) s->red[tid] += s->red[tid + off];
                __syncthreads();
            }
            if (tid == 0) g_part[sc & 1][blockIdx.x] = s->red[0];

            grid_barrier(tid);

            // deterministic reduction of the 128 per-CTA partials
            {
                const float* gp = g_part[sc & 1];
                s->red[tid] = (tid < NCTA) ? gp[tid] : 0.f;
                __syncthreads();
                #pragma unroll
                for (int off = TPB / 2; off > 0; off >>= 1) {
                    if (tid < off) s->red[tid] += s->red[tid + off];
                    __syncthreads();
                }
                if (tid == 0) s->s_ratio = sqrtf(s->red[0] / (float)NELEM);
                __syncthreads();
            }
            const float ratio = s->s_ratio;

            const bool accept = (ratio <= 1.0f);
            if (accept) {
                t = t + dt_try;
                #pragma unroll
                for (int pp = 0; pp < PPG; pp++)
                    s->Yp[p0 + pp][cB] = s->Y5p[p0 + pp][cB];   // pair-local
            }
            float factor = 0.9f * powf(fmaxf(ratio, 1e-10f), -0.2f);
            factor = fminf(fmaxf(factor, 0.2f), 10.0f);
            dt = dt * factor;
            sc++;
        }

        t = t_target;   // snap to target (matches reference)

        // write accepted state for this interval (coalesced 128B rows)
        #pragma unroll
        for (int pp = 0; pp < PPG; pp++) {
            float2 f = u2f2(s->Yp[p0 + pp][cB]);
            const size_t rg = (size_t)(row0 + 2 * (p0 + pp));
            sol[(rg * T_ + (ti + 1)) * D_ + cB]       = f.x;
            sol[((rg + 1) * T_ + (ti + 1)) * D_ + cB] = f.y;
        }
    }
}

// ---------------- decode kernel: pred = sol_z @ Wo + bo ----------------
// 64 rows per CTA, 8 rows per warp per weight pass.
#define DEC_ROWS 64
__global__ void __launch_bounds__(256)
decode_kernel(const float* __restrict__ gWo, const float* __restrict__ gbo,
              const float* __restrict__ sol_src, float* __restrict__ pred_out) {
    __shared__ float sWo[D_][O_];        // 32 KB
    __shared__ float sx[DEC_ROWS][D_];   // 16 KB   (total 48 KB static)

    const int tid = threadIdx.x;
    for (int i = tid; i < D_ * O_; i += 256) ((float*)sWo)[i] = gWo[i];

    const size_t row0 = (size_t)blockIdx.x * DEC_ROWS;
    for (int i = tid; i < DEC_ROWS * D_; i += 256)
        ((float*)sx)[i] = sol_src[row0 * D_ + i];
    __syncthreads();

    const int w = tid >> 5;
    const int l = tid & 31;
    const int rb = w * 8;                // 8 warps x 8 rows = 64 rows

    u64 a0[8], a1[8];
    {
        const u64* bop = (const u64*)gbo;           // LDG, cached
        u64 i0 = bop[2 * l], i1 = bop[2 * l + 1];
        #pragma unroll
        for (int rr = 0; rr < 8; rr++) { a0[rr] = i0; a1[rr] = i1; }
    }
    #pragma unroll 4
    for (int d0 = 0; d0 < D_; d0 += 4) {
        ulonglong2 wq[4];
        #pragma unroll
        for (int dd = 0; dd < 4; dd++)
            wq[dd] = *(const ulonglong2*)&sWo[d0 + dd][4 * l];
        float4 xv[8];
        #pragma unroll
        for (int rr = 0; rr < 8; rr++)
            xv[rr] = *(const float4*)&sx[rb + rr][d0];
        #pragma unroll
        for (int dd = 0; dd < 4; dd++) {
            #pragma unroll
            for (int rr = 0; rr < 8; rr++) {
                float x = (dd == 0) ? xv[rr].x : (dd == 1) ? xv[rr].y
                        : (dd == 2) ? xv[rr].z : xv[rr].w;
                u64 xd = dup2(x);
                a0[rr] = ffma2(xd, wq[dd].x, a0[rr]);
                a1[rr] = ffma2(xd, wq[dd].y, a1[rr]);
            }
        }
    }
    #pragma unroll
    for (int rr = 0; rr < 8; rr++) {
        const size_t r = row0 + rb + rr;
        float2 lo = u2f2(a0[rr]), hi = u2f2(a1[rr]);
        *(float4*)&pred_out[r * O_ + 4 * l] = make_float4(lo.x, lo.y, hi.x, hi.y);
    }
}

// ---------------- launch ----------------
extern "C" void kernel_launch(void* const* d_in, const int* in_sizes, int n_in,
                              void* d_out, int out_size) {
    const float* first_point = (const float*)d_in[0];
    const float* times       = (const float*)d_in[1];
    const float* W1          = (const float*)d_in[2];
    const float* b1          = (const float*)d_in[3];
    const float* W2          = (const float*)d_in[4];
    const float* b2          = (const float*)d_in[5];
    const float* Wo          = (const float*)d_in[6];
    const float* bo          = (const float*)d_in[7];

    float* out = (float*)d_out;
    const long long NS = (long long)NROW * T_ * D_;   // 12,582,912 (sol_z)
    const long long NP = (long long)NROW * T_ * O_;   // 25,165,824 (pred_x)

    float* sol_dst;
    float* pred_out;
    if ((long long)out_size == NS + NP)      { sol_dst = out;  pred_out = out + NS; }
    else if ((long long)out_size == NP) {
        // sol not in output: stage it in scratch
        float* gsol_ptr = nullptr;
        cudaGetSymbolAddress((void**)&gsol_ptr, g_sol);
        sol_dst = gsol_ptr; pred_out = out;
    }
    else if ((long long)out_size == NS)      { sol_dst = out;  pred_out = nullptr; }
    else                                     { sol_dst = out;  pred_out = out + NS; }

    cudaFuncSetAttribute(ode_kernel, cudaFuncAttributeMaxDynamicSharedMemorySize, SMEM_BYTES);

    ode_kernel<<<NCTA, TPB, SMEM_BYTES>>>(first_point, times, W1, b1, W2, b2, sol_dst);

    if (pred_out)
        decode_kernel<<<(NROW * T_) / DEC_ROWS, 256>>>(Wo, bo, sol_dst, pred_out);
}

// round 8
// speedup vs baseline: 1.6568x; 1.6568x over previous
#include <cuda_runtime.h>
#include <cuda_bf16.h>
#include <cstdint>
#include <math.h>

// ---------------- problem constants ----------------
#define S_    3
#define B_    1024
#define D_    64
#define H_    128
#define O_    128
#define T_    64
#define NROW  3072                    // S_*B_
#define NELEM (NROW * D_)             // 196608
#define RTOL_ 1e-4f
#define ATOL_ 1e-5f
#define MAX_INNER 12

// ---------------- kernel config ----------------
#define NCTA 128
#define TPB  256                      // 8 warps, 2 per SMSP
#define RPC  24                       // rows per CTA
#define RPG  6                        // rows per warp-pair group
#define RPB  3                        // stage-B rows per warp

typedef unsigned long long u64;

// ---------------- packed f32x2 helpers ----------------
__device__ __forceinline__ u64 ffma2(u64 a, u64 b, u64 c) {
    u64 d; asm("fma.rn.f32x2 %0, %1, %2, %3;" : "=l"(d) : "l"(a), "l"(b), "l"(c)); return d;
}
__device__ __forceinline__ u64 dup2(float v) {
    u64 r; asm("mov.b64 %0, {%1, %1};" : "=l"(r) : "f"(v)); return r;
}
__device__ __forceinline__ float2 u2f2(u64 v) {
    float2 f; asm("mov.b64 {%0, %1}, %2;" : "=f"(f.x), "=f"(f.y) : "l"(v)); return f;
}

// ---------------- shared memory layout (plain float arrays, round-6 style) -------
struct __align__(16) Smem {
    float W1[D_][H_];        // 32 KB   (d-major)
    float W2[H_][D_];        // 32 KB   (j-major)
    float b1[H_];
    float b2[D_];
    float Y [RPC][D_];       // 6 KB
    float Y5[RPC][D_];       // 6 KB
    float Yt[RPC][D_];       // 6 KB
    float Hh[RPC][H_];       // 12 KB
    float K [7][RPC][D_];    // 42 KB
    float red[TPB];          // 1 KB
    float s_ratio;
};
#define SMEM_BYTES ((int)sizeof(Smem))

// ---------------- device globals (scratch; no allocations allowed) ----------------
__device__ unsigned g_bar = 0;                         // monotone barrier counter
__device__ float    g_part[2][NCTA];                   // per-CTA partial err sums
__device__ float    g_sol[(size_t)NROW * T_ * D_];     // fallback sol_z scratch

// ---------------- grid-wide barrier (all NCTA CTAs co-resident) ----------------
__device__ __forceinline__ void grid_barrier(int tid) {
    __syncthreads();
    if (tid == 0) {
        __threadfence();
        unsigned arrival = atomicAdd(&g_bar, 1u);
        unsigned target = arrival - (arrival % NCTA) + NCTA;
        while ((int)(*(volatile unsigned*)&g_bar - target) < 0) {
            __nanosleep(64);
        }
        __threadfence();
    }
    __syncthreads();
}

// ---------------- f(Yin) -> Kout ------------------------------------------------
// group g (warps 2g, 2g+1) owns rows 6g..6g+5.
// stage A: warp half h covers H-cols [64h, 64h+64), 2 cols/lane, all 6 rows.
// stage B: warp half h covers rows 6g+3h..6g+3h+2, all 64 D-cols, 2 cols/lane.
__device__ __forceinline__ void feval(Smem* s, int g, int h, int l,
                                      const float (*Yin)[D_], float (*Kout)[D_]) {
    __syncthreads();                       // Yin fully written (cross-warp rows)
    const int rg0 = RPG * g;
    const int cA = 64 * h + 2 * l;

    // ---- stage A: Hh[:, cA..cA+1] = tanh(Yin @ W1 + b1) ----
    u64 acc[RPG];
    {
        u64 bias = *(const u64*)&s->b1[cA];
        #pragma unroll
        for (int rr = 0; rr < RPG; rr++) acc[rr] = bias;
    }
    #pragma unroll 4
    for (int d0 = 0; d0 < D_; d0 += 4) {
        u64 wv[4];
        #pragma unroll
        for (int dd = 0; dd < 4; dd++)
            wv[dd] = *(const u64*)&s->W1[d0 + dd][cA];        // LDS.64 conflict-free
        float4 yv[RPG];
        #pragma unroll
        for (int rr = 0; rr < RPG; rr++)
            yv[rr] = *(const float4*)&Yin[rg0 + rr][d0];      // LDS.128 broadcast
        #pragma unroll
        for (int dd = 0; dd < 4; dd++) {
            #pragma unroll
            for (int rr = 0; rr < RPG; rr++) {
                float y = (dd == 0) ? yv[rr].x : (dd == 1) ? yv[rr].y
                        : (dd == 2) ? yv[rr].z : yv[rr].w;
                acc[rr] = ffma2(dup2(y), wv[dd], acc[rr]);
            }
        }
    }
    #pragma unroll
    for (int rr = 0; rr < RPG; rr++) {
        float2 v = u2f2(acc[rr]);
        float2 hv = make_float2(tanhf(v.x), tanhf(v.y));
        *(float2*)&s->Hh[rg0 + rr][cA] = hv;                  // STS.64 conflict-free
    }
    __syncthreads();                       // Hh fully written (cross-warp cols)

    // ---- stage B: Kout[rB, 2l..2l+1] = Hh @ W2 + b2 ----
    const int rB0 = rg0 + RPB * h;
    u64 a2[RPB];
    {
        u64 bias2 = *(const u64*)&s->b2[2 * l];
        #pragma unroll
        for (int rr = 0; rr < RPB; rr++) a2[rr] = bias2;
    }
    #pragma unroll 4
    for (int j0 = 0; j0 < H_; j0 += 4) {
        u64 w2v[4];
        #pragma unroll
        for (int dd = 0; dd < 4; dd++)
            w2v[dd] = *(const u64*)&s->W2[j0 + dd][2 * l];    // LDS.64 conflict-free
        float4 hv4[RPB];
        #pragma unroll
        for (int rr = 0; rr < RPB; rr++)
            hv4[rr] = *(const float4*)&s->Hh[rB0 + rr][j0];   // LDS.128 broadcast
        #pragma unroll
        for (int dd = 0; dd < 4; dd++) {
            #pragma unroll
            for (int rr = 0; rr < RPB; rr++) {
                float hsc = (dd == 0) ? hv4[rr].x : (dd == 1) ? hv4[rr].y
                          : (dd == 2) ? hv4[rr].z : hv4[rr].w;
                a2[rr] = ffma2(dup2(hsc), w2v[dd], a2[rr]);
            }
        }
    }
    #pragma unroll
    for (int rr = 0; rr < RPB; rr++) {
        float2 v = u2f2(a2[rr]);
        *(float2*)&Kout[rB0 + rr][2 * l] = v;                 // thread-local consumers
    }
}

// ---- Out = Y + dt * sum(cf[kk]*K[kk]) over this thread's rows/cols ----
template <int NK>
__device__ __forceinline__ void build_stage(Smem* s, int rB0, int l, float dtv,
                                            const float* cf, float (*Out)[D_]) {
    #pragma unroll
    for (int rr = 0; rr < RPB; rr++) {
        const int r = rB0 + rr;
        #pragma unroll
        for (int c = 0; c < 2; c++) {
            const int d = 2 * l + c;
            float acc = 0.f;
            #pragma unroll
            for (int kk = 0; kk < NK; kk++)
                acc = fmaf(cf[kk], s->K[kk][r][d], acc);
            Out[r][d] = fmaf(dtv, acc, s->Y[r][d]);
        }
    }
}

// ---------------- persistent ODE solver kernel ----------------
__global__ void __launch_bounds__(TPB, 1)
ode_kernel(const float* __restrict__ first_point,
           const float* __restrict__ times,
           const float* __restrict__ gW1, const float* __restrict__ gb1,
           const float* __restrict__ gW2, const float* __restrict__ gb2,
           float* __restrict__ sol) {
    extern __shared__ char smem_raw[];
    Smem* s = (Smem*)smem_raw;

    const int tid = threadIdx.x;
    const int w = tid >> 5;
    const int l = tid & 31;
    const int g = w >> 1;
    const int h = w & 1;
    const int row0 = blockIdx.x * RPC;
    const int rB0 = RPG * g + RPB * h;     // this thread's 3 owned rows

    // load weights + initial state
    for (int i = tid; i < D_ * H_; i += TPB) ((float*)s->W1)[i] = gW1[i];
    for (int i = tid; i < H_ * D_; i += TPB) ((float*)s->W2)[i] = gW2[i];
    for (int i = tid; i < H_; i += TPB) s->b1[i] = gb1[i];
    for (int i = tid; i < D_; i += TPB) s->b2[i] = gb2[i];
    for (int i = tid; i < RPC * D_; i += TPB)
        ((float*)s->Y)[i] = first_point[(size_t)row0 * D_ + i];
    __syncthreads();

    // sol at t index 0 (coalesced 256B row segments)
    #pragma unroll
    for (int rr = 0; rr < RPB; rr++) {
        const int r = rB0 + rr;
        float2 v = *(const float2*)&s->Y[r][2 * l];
        *(float2*)&sol[((size_t)(row0 + r) * T_ + 0) * D_ + 2 * l] = v;
    }

    // dopri5 coefficients
    const float C2[1] = {0.2f};
    const float C3[2] = {3.f / 40.f, 9.f / 40.f};
    const float C4[3] = {44.f / 45.f, -56.f / 15.f, 32.f / 9.f};
    const float C5[4] = {19372.f / 6561.f, -25360.f / 2187.f, 64448.f / 6561.f, -212.f / 729.f};
    const float C6[5] = {9017.f / 3168.f, -355.f / 33.f, 46732.f / 5247.f, 49.f / 176.f,
                         -5103.f / 18656.f};
    const float CB[6] = {35.f / 384.f, 0.f, 500.f / 1113.f, 125.f / 192.f,
                         -2187.f / 6784.f, 11.f / 84.f};
    const float E1 = 71.f / 57600.f, E3 = -71.f / 16695.f, E4 = 71.f / 1920.f;
    const float E5 = -17253.f / 339200.f, E6 = 22.f / 525.f, E7 = -1.f / 40.f;

    float t  = times[0];
    float dt = times[1] - times[0];
    int sc = 0;   // executed-step counter (uniform across CTAs)

    for (int ti = 0; ti < T_ - 1; ti++) {
        const float t_target = times[ti + 1];

        for (int iter = 0; iter < MAX_INNER; iter++) {
            const float remaining = t_target - t;
            if (remaining <= 0.0f) break;              // remaining iters are exact no-ops
            const float dt_try = fminf(dt, remaining);

            // 7 stages
            feval(s, g, h, l, s->Y, s->K[0]);
            build_stage<1>(s, rB0, l, dt_try, C2, s->Yt); feval(s, g, h, l, s->Yt, s->K[1]);
            build_stage<2>(s, rB0, l, dt_try, C3, s->Yt); feval(s, g, h, l, s->Yt, s->K[2]);
            build_stage<3>(s, rB0, l, dt_try, C4, s->Yt); feval(s, g, h, l, s->Yt, s->K[3]);
            build_stage<4>(s, rB0, l, dt_try, C5, s->Yt); feval(s, g, h, l, s->Yt, s->K[4]);
            build_stage<5>(s, rB0, l, dt_try, C6, s->Yt); feval(s, g, h, l, s->Yt, s->K[5]);
            build_stage<6>(s, rB0, l, dt_try, CB, s->Y5); feval(s, g, h, l, s->Y5, s->K[6]);

            // local error accumulation over this thread's 3 rows x 2 cols
            float local = 0.f;
            #pragma unroll
            for (int rr = 0; rr < RPB; rr++) {
                const int r = rB0 + rr;
                #pragma unroll
                for (int c = 0; c < 2; c++) {
                    const int d = 2 * l + c;
                    float e = E1 * s->K[0][r][d];
                    e = fmaf(E3, s->K[2][r][d], e);
                    e = fmaf(E4, s->K[3][r][d], e);
                    e = fmaf(E5, s->K[4][r][d], e);
                    e = fmaf(E6, s->K[5][r][d], e);
                    e = fmaf(E7, s->K[6][r][d], e);
                    e *= dt_try;
                    float scale = ATOL_ + RTOL_ * fmaxf(fabsf(s->Y[r][d]), fabsf(s->Y5[r][d]));
                    float q = e / scale;
                    local = fmaf(q, q, local);
                }
            }

            // deterministic CTA tree reduction
            s->red[tid] = local;
            __syncthreads();
            #pragma unroll
            for (int off = TPB / 2; off > 0; off >>= 1) {
                if (tid < off) s->red[tid] += s->red[tid + off];
                __syncthreads();
            }
            if (tid == 0) g_part[sc & 1][blockIdx.x] = s->red[0];

            grid_barrier(tid);

            // deterministic reduction of the 128 per-CTA partials
            {
                const float* gp = g_part[sc & 1];
                s->red[tid] = (tid < NCTA) ? gp[tid] : 0.f;
                __syncthreads();
                #pragma unroll
                for (int off = TPB / 2; off > 0; off >>= 1) {
                    if (tid < off) s->red[tid] += s->red[tid + off];
                    __syncthreads();
                }
                if (tid == 0) s->s_ratio = sqrtf(s->red[0] / (float)NELEM);
                __syncthreads();
            }
            const float ratio = s->s_ratio;

            const bool accept = (ratio <= 1.0f);
            if (accept) {
                t = t + dt_try;
                #pragma unroll
                for (int rr = 0; rr < RPB; rr++) {
                    const int r = rB0 + rr;
                    *(float2*)&s->Y[r][2 * l] = *(const float2*)&s->Y5[r][2 * l];
                }
            }
            float factor = 0.9f * powf(fmaxf(ratio, 1e-10f), -0.2f);
            factor = fminf(fmaxf(factor, 0.2f), 10.0f);
            dt = dt * factor;
            sc++;
        }

        t = t_target;   // snap to target (matches reference)

        // write accepted state for this interval (coalesced)
        __syncwarp();
        #pragma unroll
        for (int rr = 0; rr < RPB; rr++) {
            const int r = rB0 + rr;
            float2 v = *(const float2*)&s->Y[r][2 * l];
            *(float2*)&sol[((size_t)(row0 + r) * T_ + (ti + 1)) * D_ + 2 * l] = v;
        }
    }
}

// ---------------- decode kernel: pred = sol_z @ Wo + bo (round-6 proven shape) ----
#define DEC_ROWS 32
__global__ void __launch_bounds__(256)
decode_kernel(const float* __restrict__ gWo, const float* __restrict__ gbo,
              const float* __restrict__ sol_src, float* __restrict__ pred_out) {
    __shared__ float sWo[D_][O_];        // 32 KB
    __shared__ float sbo[O_];
    __shared__ float sx[DEC_ROWS][D_];   // 8 KB

    const int tid = threadIdx.x;
    for (int i = tid; i < D_ * O_; i += 256) ((float*)sWo)[i] = gWo[i];
    for (int i = tid; i < O_; i += 256) sbo[i] = gbo[i];

    const size_t row0 = (size_t)blockIdx.x * DEC_ROWS;
    for (int i = tid; i < DEC_ROWS * D_; i += 256)
        ((float*)sx)[i] = sol_src[row0 * D_ + i];
    __syncthreads();

    const int w = tid >> 5;
    const int l = tid & 31;
    const int rb = w * 4;                // 8 warps x 4 rows = 32 rows

    u64 a0[4], a1[4];
    {
        const u64* bop = (const u64*)sbo;
        u64 i0 = bop[2 * l], i1 = bop[2 * l + 1];
        #pragma unroll
        for (int rr = 0; rr < 4; rr++) { a0[rr] = i0; a1[rr] = i1; }
    }
    #pragma unroll 4
    for (int d0 = 0; d0 < D_; d0 += 4) {
        ulonglong2 wq[4];
        #pragma unroll
        for (int dd = 0; dd < 4; dd++)
            wq[dd] = *(const ulonglong2*)&sWo[d0 + dd][4 * l];
        float4 xv[4];
        #pragma unroll
        for (int rr = 0; rr < 4; rr++)
            xv[rr] = *(const float4*)&sx[rb + rr][d0];
        #pragma unroll
        for (int dd = 0; dd < 4; dd++) {
            #pragma unroll
            for (int rr = 0; rr < 4; rr++) {
                float x = (dd == 0) ? xv[rr].x : (dd == 1) ? xv[rr].y
                        : (dd == 2) ? xv[rr].z : xv[rr].w;
                u64 xd = dup2(x);
                a0[rr] = ffma2(xd, wq[dd].x, a0[rr]);
                a1[rr] = ffma2(xd, wq[dd].y, a1[rr]);
            }
        }
    }
    #pragma unroll
    for (int rr = 0; rr < 4; rr++) {
        const size_t r = row0 + rb + rr;
        float2 lo = u2f2(a0[rr]), hi = u2f2(a1[rr]);
        *(float4*)&pred_out[r * O_ + 4 * l] = make_float4(lo.x, lo.y, hi.x, hi.y);
    }
}

// ---------------- launch ----------------
extern "C" void kernel_launch(void* const* d_in, const int* in_sizes, int n_in,
                              void* d_out, int out_size) {
    const float* first_point = (const float*)d_in[0];
    const float* times       = (const float*)d_in[1];
    const float* W1          = (const float*)d_in[2];
    const float* b1          = (const float*)d_in[3];
    const float* W2          = (const float*)d_in[4];
    const float* b2          = (const float*)d_in[5];
    const float* Wo          = (const float*)d_in[6];
    const float* bo          = (const float*)d_in[7];

    float* out = (float*)d_out;
    const long long NS = (long long)NROW * T_ * D_;   // 12,582,912 (sol_z)
    const long long NP = (long long)NROW * T_ * O_;   // 25,165,824 (pred_x)

    float* sol_dst;
    float* pred_out;
    if ((long long)out_size == NS + NP)      { sol_dst = out;  pred_out = out + NS; }
    else if ((long long)out_size == NP) {
        float* gsol_ptr = nullptr;
        cudaGetSymbolAddress((void**)&gsol_ptr, g_sol);
        sol_dst = gsol_ptr; pred_out = out;
    }
    else if ((long long)out_size == NS)      { sol_dst = out;  pred_out = nullptr; }
    else                                     { sol_dst = out;  pred_out = out + NS; }

    cudaFuncSetAttribute(ode_kernel, cudaFuncAttributeMaxDynamicSharedMemorySize, SMEM_BYTES);

    ode_kernel<<<NCTA, TPB, SMEM_BYTES>>>(first_point, times, W1, b1, W2, b2, sol_dst);

    if (pred_out)
        decode_kernel<<<(NROW * T_) / DEC_ROWS, 256>>>(Wo, bo, sol_dst, pred_out);
}